// round 16
// baseline (speedup 1.0000x reference)
#include <cuda_runtime.h>
#include <cuda_fp16.h>
#include <math.h>
#include <stdint.h>

// ---------------------------------------------------------------------------
// BlockKoopmanNet — fp16 tensor-core GEMMs (mma.sync.m16n8k16.f16, fp32
// accumulate), ldmatrix fragment loads with SOFTWARE-PIPELINED double-
// buffered fragments, cp.async 4-stage pipeline. Weights pre-transposed to
// half [N,K]; activations flow as half. B=16384, X=64, U=16, Z=32, H=1024.
// ---------------------------------------------------------------------------

#define KDT 0.02f
#define BATCH 16384

// Scratch (allocation-free rule: __device__ globals).
__device__ __half g_bufA[BATCH * 1024];
__device__ __half g_bufB[BATCH * 1024];
__device__ __half g_s1[BATCH * 256];
__device__ __half g_s2[BATCH * 256];
__device__ float  g_z[BATCH * 32];
__device__ float  g_aux[BATCH * 32];
__device__ __half g_Bmat[BATCH * 512];
__device__ __half g_znext[BATCH * 32];
__device__ __half g_xh[BATCH * 64];         // half-converted x
__device__ __half g_wh[3645440];            // half, transposed [N,K] weights

__device__ __forceinline__ void mma16(float* d, const uint32_t* a, const uint32_t* b) {
    asm volatile(
        "mma.sync.aligned.m16n8k16.row.col.f32.f16.f16.f32 "
        "{%0,%1,%2,%3}, {%4,%5,%6,%7}, {%8,%9}, {%0,%1,%2,%3};"
        : "+f"(d[0]), "+f"(d[1]), "+f"(d[2]), "+f"(d[3])
        : "r"(a[0]), "r"(a[1]), "r"(a[2]), "r"(a[3]), "r"(b[0]), "r"(b[1]));
}

__device__ __forceinline__ void ldsm4(uint32_t& r0, uint32_t& r1,
                                      uint32_t& r2, uint32_t& r3, uint32_t addr) {
    asm volatile("ldmatrix.sync.aligned.m8n8.x4.shared.b16 {%0,%1,%2,%3}, [%4];"
                 : "=r"(r0), "=r"(r1), "=r"(r2), "=r"(r3) : "r"(addr));
}

__device__ __forceinline__ void cpa16(uint32_t dst, const void* src) {
    asm volatile("cp.async.cg.shared.global [%0], [%1], 16;" :: "r"(dst), "l"(src));
}
__device__ __forceinline__ void cpa_commit() {
    asm volatile("cp.async.commit_group;" ::: "memory");
}
__device__ __forceinline__ void cpa_wait2() {
    asm volatile("cp.async.wait_group 2;" ::: "memory");
}

// ---------------------------------------------------------------------------
// Prep 1: convert x to half.
// ---------------------------------------------------------------------------
__global__ void convert_x(const float4* __restrict__ src,
                          __half2* __restrict__ dst, int n4)
{
    int i = blockIdx.x * blockDim.x + threadIdx.x;
    const int stride = gridDim.x * blockDim.x;
    for (; i < n4; i += stride) {
        float4 v = src[i];
        dst[i * 2 + 0] = __floats2half2_rn(v.x, v.y);
        dst[i * 2 + 1] = __floats2half2_rn(v.z, v.w);
    }
}

// ---------------------------------------------------------------------------
// Prep 2: transpose + convert — WT[n][k] = half(W[k][n]) for ALL 13 weights.
// ---------------------------------------------------------------------------
#define NTSEG 13
struct TSeg { const float* src; __half* dst; int K; int N; };
struct TSegPack { TSeg s[NTSEG]; };

__global__ void transpose_half(TSegPack p)
{
    const TSeg sg = p.s[blockIdx.z];
    const int n0 = blockIdx.x * 32, k0 = blockIdx.y * 32;
    if (n0 >= sg.N || k0 >= sg.K) return;
    __shared__ float tile[32][33];
    const int x = threadIdx.x, y = threadIdx.y;
#pragma unroll
    for (int i = 0; i < 4; i++)
        tile[y + i * 8][x] = sg.src[(size_t)(k0 + y + i * 8) * sg.N + n0 + x];
    __syncthreads();
#pragma unroll
    for (int i = 0; i < 4; i++)
        sg.dst[(size_t)(n0 + y + i * 8) * sg.K + k0 + x] =
            __float2half_rn(tile[x][y + i * 8]);
}

// ---------------------------------------------------------------------------
// C = act(A[M,K] @ WT[N,K]^T + bias). A half row-major, WT half [N,K].
// BM=128, BK=32 (2 x k16 steps), 8 warps, S=4 cp.async stages.
// Fragment double buffer: frags for k-step u+1 are ldmatrix'd while MMAs for
// step u issue; the tile-(t+1) wait+sync sits between the two MMA half-steps
// of tile t so the barrier drains under tensor-pipe work.
// OUTH: store half (feeds next GEMM); else float.
// ---------------------------------------------------------------------------
template <int BN, int WM, int WN, bool ACT, bool OUTH>
__global__ void __launch_bounds__(256, 2)
gemm_fp16(const __half* __restrict__ A, const __half* __restrict__ WT,
          const float* __restrict__ bias, void* __restrict__ Cv,
          int M, int N, int K)
{
    constexpr int BM = 128, BK = 32, S = 4;
    constexpr int MT = WM / 16;
    constexpr int NT = WN / 8;
    static_assert(NT % 2 == 0, "B ldmatrix.x4 covers n-tile pairs");
    constexpr int WARPS_N = BN / WN;
    constexpr int WARPS_M = 8 / WARPS_N;
    static_assert(WARPS_M * WM == BM, "warp grid must tile BM exactly");
    static_assert(WARPS_N * WN == BN, "warp grid must tile BN exactly");
    constexpr int STR = 20;                       // words per row (A and WT)
    constexpr int AWORDS = BM * STR;
    constexpr int WWORDS = BN * STR;
    constexpr int AV = (BM * 4) / 256;            // 16B chunks per thread (A)
    constexpr int WTOT = BN * 4;                  // 16B chunks in W tile
    constexpr int WV = (WTOT + 255) / 256;
    constexpr bool WGUARD = (WTOT % 256) != 0;

    extern __shared__ uint32_t smem_dyn[];
    uint32_t* Asm = smem_dyn;
    uint32_t* Wsm = smem_dyn + S * AWORDS;

    const int tid  = threadIdx.x;
    const int lane = tid & 31;
    const int wid  = tid >> 5;
    const int wm   = wid / WARPS_N;
    const int wn   = wid % WARPS_N;
    const int brow = blockIdx.y * BM;
    const int bcol = blockIdx.x * BN;
    const int g    = lane >> 2;
    const int tg   = lane & 3;

    // ldmatrix lane roles (quadrant q = lane/8, r = lane%8).
    const int q  = lane >> 3;
    const int rr = lane & 7;
    const int a_row = ((q & 1) << 3) + rr;
    const int a_col = (q >> 1) << 2;
    const int b_row = ((q >> 1) << 3) + rr;
    const int b_col = (q & 1) << 2;

    const uint32_t a_sm = (uint32_t)__cvta_generic_to_shared(Asm);
    const uint32_t w_sm = (uint32_t)__cvta_generic_to_shared(Wsm);
    const int nk = K / BK;

    float acc[MT][NT][4];
#pragma unroll
    for (int m = 0; m < MT; m++)
#pragma unroll
        for (int n = 0; n < NT; n++)
#pragma unroll
            for (int qq = 0; qq < 4; qq++) acc[m][n][qq] = 0.0f;

    uint32_t afb[2][MT][4];
    uint32_t bfb[2][NT][2];

    auto issue_tile = [&](int t) {
        if (t < nk) {
            const int s  = t % S;
            const int k0 = t * BK;
            const uint32_t ab = a_sm + (uint32_t)s * AWORDS * 4;
            const uint32_t wb = w_sm + (uint32_t)s * WWORDS * 4;
#pragma unroll
            for (int v = 0; v < AV; v++) {
                int idx = tid + v * 256;
                int row = idx >> 2, ch = idx & 3;
                cpa16(ab + (uint32_t)(row * STR + ch * 4) * 4,
                      A + (size_t)(brow + row) * K + k0 + ch * 8);
            }
#pragma unroll
            for (int v = 0; v < WV; v++) {
                int idx = tid + v * 256;
                if (!WGUARD || idx < WTOT) {
                    int row = idx >> 2, ch = idx & 3;
                    cpa16(wb + (uint32_t)(row * STR + ch * 4) * 4,
                          WT + (size_t)(bcol + row) * K + k0 + ch * 8);
                }
            }
        }
        cpa_commit();
    };

    auto load_frags = [&](int buf, int stage, int ks) {
        const uint32_t a_st = a_sm + (uint32_t)stage * AWORDS * 4;
        const uint32_t w_st = w_sm + (uint32_t)stage * WWORDS * 4;
#pragma unroll
        for (int m = 0; m < MT; m++) {
            const int r0 = wm * WM + m * 16;
            ldsm4(afb[buf][m][0], afb[buf][m][1], afb[buf][m][2], afb[buf][m][3],
                  a_st + (uint32_t)((r0 + a_row) * STR + ks * 8 + a_col) * 4);
        }
#pragma unroll
        for (int p = 0; p < NT / 2; p++) {
            const int cb0 = wn * WN + p * 16;
            ldsm4(bfb[buf][2 * p][0], bfb[buf][2 * p][1],
                  bfb[buf][2 * p + 1][0], bfb[buf][2 * p + 1][1],
                  w_st + (uint32_t)((cb0 + b_row) * STR + ks * 8 + b_col) * 4);
        }
    };

    auto mma_all = [&](int buf) {
#pragma unroll
        for (int m = 0; m < MT; m++)
#pragma unroll
            for (int n = 0; n < NT; n++)
                mma16(acc[m][n], afb[buf][m], bfb[buf][n]);
    };

    issue_tile(0);
    issue_tile(1);
    issue_tile(2);
    cpa_wait2();
    __syncthreads();
    load_frags(0, 0, 0);                 // tile 0, ks0

    for (int t = 0; t < nk; t++) {
        const int s = t % S;
        load_frags(1, s, 1);             // tile t, ks1 (smem resident)
        issue_tile(t + 3);               // overwrites stage (t-1)%4: safe,
                                         // last reads preceded sync(t-1)
        mma_all(0);                      // tile t, ks0

        if (t + 1 < nk) {
            cpa_wait2();                 // tile t+1 resident
            __syncthreads();
            load_frags(0, (t + 1) % S, 0);
        }
        mma_all(1);                      // tile t, ks1
    }

    // ---- epilogue: bias (+ SiLU); store half or float ----
#pragma unroll
    for (int m = 0; m < MT; m++) {
#pragma unroll
        for (int n = 0; n < NT; n++) {
            const int r0 = brow + wm * WM + m * 16 + g;
            const int cc = bcol + wn * WN + n * 8 + tg * 2;
            const float b0 = bias[cc], b1 = bias[cc + 1];
            float v0 = acc[m][n][0] + b0;
            float v1 = acc[m][n][1] + b1;
            float v2 = acc[m][n][2] + b0;
            float v3 = acc[m][n][3] + b1;
            if (ACT) {
                v0 = v0 / (1.0f + __expf(-v0));
                v1 = v1 / (1.0f + __expf(-v1));
                v2 = v2 / (1.0f + __expf(-v2));
                v3 = v3 / (1.0f + __expf(-v3));
            }
            if (OUTH) {
                __half* C = (__half*)Cv;
                *reinterpret_cast<__half2*>(C + (size_t)r0 * N + cc) =
                    __floats2half2_rn(v0, v1);
                *reinterpret_cast<__half2*>(C + (size_t)(r0 + 8) * N + cc) =
                    __floats2half2_rn(v2, v3);
            } else {
                float* C = (float*)Cv;
                float2 lo = {v0, v1}, hi = {v2, v3};
                *reinterpret_cast<float2*>(C + (size_t)r0 * N + cc) = lo;
                *reinterpret_cast<float2*>(C + (size_t)(r0 + 8) * N + cc) = hi;
            }
        }
    }
}

// ---------------------------------------------------------------------------
// Combine: z_next = half(z + DT*(Az + Bu)); Bmat is half.
// ---------------------------------------------------------------------------
__global__ void combine_kernel(const float* __restrict__ z,
                               const float* __restrict__ aux,
                               const __half* __restrict__ Bmat,
                               const float* __restrict__ u,
                               __half* __restrict__ z_next)
{
    const int row  = blockIdx.x * (blockDim.x >> 5) + (threadIdx.x >> 5);
    const int lane = threadIdx.x & 31;
    if (row >= BATCH) return;

    const int j = lane;
    const int i = j >> 1;

    const float a  = aux[row * 32 + 2 * i];
    const float bb = aux[row * 32 + 2 * i + 1];
    const float z0 = z[row * 32 + 2 * i];
    const float z1 = z[row * 32 + 2 * i + 1];

    const float f = expf(a * KDT);
    const float c = cosf(bb * KDT);
    const float s = sinf(bb * KDT);

    const float az = (j & 1) ? f * (s * z0 + c * z1)
                             : f * (c * z0 - s * z1);
    const float zj = (j & 1) ? z1 : z0;

    const __half2* bm = reinterpret_cast<const __half2*>(
        Bmat + (size_t)row * 512 + j * 16);
    const float* ur = u + (size_t)row * 16;
    float bu = 0.0f;
#pragma unroll
    for (int k = 0; k < 8; k++) {
        float2 w = __half22float2(bm[k]);
        bu = fmaf(w.x, ur[2 * k],     bu);
        bu = fmaf(w.y, ur[2 * k + 1], bu);
    }

    z_next[row * 32 + j] = __float2half_rn(zj + KDT * (az + bu));
}

// ---------------------------------------------------------------------------
static constexpr int smem_fp16(int BN) {
    return 4 * (128 * 20 + BN * 20) * 4;   // S=4, stride 20 words
}

extern "C" void kernel_launch(void* const* d_in, const int* in_sizes, int n_in,
                              void* d_out, int out_size)
{
    const float* x    = (const float*)d_in[0];
    const float* u    = (const float*)d_in[1];
    const float* e_w1 = (const float*)d_in[2];
    const float* e_b1 = (const float*)d_in[3];
    const float* e_w2 = (const float*)d_in[4];
    const float* e_b2 = (const float*)d_in[5];
    const float* e_w3 = (const float*)d_in[6];
    const float* e_b3 = (const float*)d_in[7];
    const float* d_w1 = (const float*)d_in[8];
    const float* d_b1 = (const float*)d_in[9];
    const float* d_w2 = (const float*)d_in[10];
    const float* d_b2 = (const float*)d_in[11];
    const float* d_w3 = (const float*)d_in[12];
    const float* d_b3 = (const float*)d_in[13];
    const float* d_w4 = (const float*)d_in[14];
    const float* d_b4 = (const float*)d_in[15];
    const float* a_w1 = (const float*)d_in[16];
    const float* a_b1 = (const float*)d_in[17];
    const float* a_w2 = (const float*)d_in[18];
    const float* a_b2 = (const float*)d_in[19];
    const float* a_w3 = (const float*)d_in[20];
    const float* a_b3 = (const float*)d_in[21];
    const float* b_w1 = (const float*)d_in[22];
    const float* b_b1 = (const float*)d_in[23];
    const float* b_w2 = (const float*)d_in[24];
    const float* b_b2 = (const float*)d_in[25];
    const float* b_w3 = (const float*)d_in[26];
    const float* b_b3 = (const float*)d_in[27];
    float* out = (float*)d_out;

    __half *bufA, *bufB, *s1, *s2, *zn, *xh, *wh, *Bm;
    float  *zb, *auxb;
    cudaGetSymbolAddress((void**)&bufA, g_bufA);
    cudaGetSymbolAddress((void**)&bufB, g_bufB);
    cudaGetSymbolAddress((void**)&s1,   g_s1);
    cudaGetSymbolAddress((void**)&s2,   g_s2);
    cudaGetSymbolAddress((void**)&zb,   g_z);
    cudaGetSymbolAddress((void**)&auxb, g_aux);
    cudaGetSymbolAddress((void**)&Bm,   g_Bmat);
    cudaGetSymbolAddress((void**)&zn,   g_znext);
    cudaGetSymbolAddress((void**)&xh,   g_xh);
    cudaGetSymbolAddress((void**)&wh,   g_wh);

    // Transposed half weights in g_wh (offsets in halves).
    __half* e_w1t = wh + 0;          // [1024][64]
    __half* e_w2t = wh + 65536;      // [1024][1024]
    __half* e_w3t = wh + 1114112;    // [32][1024]
    __half* d_w1t = wh + 1146880;    // [1024][32]
    __half* d_w2t = wh + 1179648;    // [1024][1024]
    __half* d_w3t = wh + 2228224;    // [1024][1024]
    __half* d_w4t = wh + 3276800;    // [64][1024]
    __half* a_w1t = wh + 3342336;    // [256][64]
    __half* a_w2t = wh + 3358720;    // [256][256]
    __half* a_w3t = wh + 3424256;    // [32][256]
    __half* b_w1t = wh + 3432448;    // [256][64]
    __half* b_w2t = wh + 3448832;    // [256][256]
    __half* b_w3t = wh + 3514368;    // [512][256]

    // ---- prep: convert x + transpose/convert all weights (2 launches) ----
    convert_x<<<256, 256>>>((const float4*)x, (__half2*)xh, BATCH * 64 / 4);
    {
        TSegPack p;
        auto set = [&](int i, const float* s, __half* d, int K, int N) {
            p.s[i].src = s; p.s[i].dst = d; p.s[i].K = K; p.s[i].N = N;
        };
        set(0,  e_w1, e_w1t,   64, 1024);
        set(1,  e_w2, e_w2t, 1024, 1024);
        set(2,  e_w3, e_w3t, 1024,   32);
        set(3,  d_w1, d_w1t,   32, 1024);
        set(4,  d_w2, d_w2t, 1024, 1024);
        set(5,  d_w3, d_w3t, 1024, 1024);
        set(6,  d_w4, d_w4t, 1024,   64);
        set(7,  a_w1, a_w1t,   64,  256);
        set(8,  a_w2, a_w2t,  256,  256);
        set(9,  a_w3, a_w3t,  256,   32);
        set(10, b_w1, b_w1t,   64,  256);
        set(11, b_w2, b_w2t,  256,  256);
        set(12, b_w3, b_w3t,  256,  512);
        transpose_half<<<dim3(32, 32, NTSEG), dim3(32, 8)>>>(p);
    }

    const int B  = BATCH;
    const int GY = B / 128;
    const dim3 blk(256);

    constexpr int SM_BIG   = smem_fp16(128);   // 81,920 B
    constexpr int SM_MID   = smem_fp16(64);    // 61,440 B
    constexpr int SM_SMALL = smem_fp16(32);    // 51,200 B

    auto big_t   = gemm_fp16<128, 64, 32, true,  true >;   // ACT -> half out
    auto big_h   = gemm_fp16<128, 64, 32, false, true >;   // b_w3 -> half
    auto mid_f   = gemm_fp16< 64, 32, 32, false, false>;   // d_w4 -> float
    auto small_f = gemm_fp16< 32, 16, 32, false, false>;   // e_w3/a_w3 -> float

    cudaFuncSetAttribute(big_t,   cudaFuncAttributeMaxDynamicSharedMemorySize, SM_BIG);
    cudaFuncSetAttribute(big_h,   cudaFuncAttributeMaxDynamicSharedMemorySize, SM_BIG);
    cudaFuncSetAttribute(mid_f,   cudaFuncAttributeMaxDynamicSharedMemorySize, SM_MID);
    cudaFuncSetAttribute(small_f, cudaFuncAttributeMaxDynamicSharedMemorySize, SM_SMALL);

    // ---- encoder: x -> h1 -> h2 -> z ----
    big_t  <<<dim3(8, GY), blk, SM_BIG  >>>(xh,   e_w1t, e_b1, bufA, B, 1024,   64);
    big_t  <<<dim3(8, GY), blk, SM_BIG  >>>(bufA, e_w2t, e_b2, bufB, B, 1024, 1024);
    small_f<<<dim3(1, GY), blk, SM_SMALL>>>(bufB, e_w3t, e_b3, zb,   B,   32, 1024);

    // ---- aux net ----
    big_t  <<<dim3(2, GY), blk, SM_BIG  >>>(xh, a_w1t, a_b1, s1,   B, 256,  64);
    big_t  <<<dim3(2, GY), blk, SM_BIG  >>>(s1, a_w2t, a_b2, s2,   B, 256, 256);
    small_f<<<dim3(1, GY), blk, SM_SMALL>>>(s2, a_w3t, a_b3, auxb, B,  32, 256);

    // ---- B net ----
    big_t  <<<dim3(2, GY), blk, SM_BIG  >>>(xh, b_w1t, b_b1, s1, B, 256,  64);
    big_t  <<<dim3(2, GY), blk, SM_BIG  >>>(s1, b_w2t, b_b2, s2, B, 256, 256);
    big_h  <<<dim3(4, GY), blk, SM_BIG  >>>(s2, b_w3t, b_b3, Bm, B, 512, 256);

    // ---- dynamics combine (half z_next for decoder) ----
    combine_kernel<<<B / 8, 256>>>(zb, auxb, Bm, u, zn);

    // ---- decoder ----
    big_t  <<<dim3(8, GY), blk, SM_BIG  >>>(zn,   d_w1t, d_b1, bufA, B, 1024,   32);
    big_t  <<<dim3(8, GY), blk, SM_BIG  >>>(bufA, d_w2t, d_b2, bufB, B, 1024, 1024);
    big_t  <<<dim3(8, GY), blk, SM_BIG  >>>(bufB, d_w3t, d_b3, bufA, B, 1024, 1024);
    mid_f  <<<dim3(1, GY), blk, SM_MID  >>>(bufA, d_w4t, d_b4, out,  B,   64, 1024);
}

// round 17
// speedup vs baseline: 1.6478x; 1.6478x over previous
#include <cuda_runtime.h>
#include <cuda_fp16.h>
#include <math.h>
#include <stdint.h>

// ---------------------------------------------------------------------------
// BlockKoopmanNet — fp16 tensor-core GEMMs (mma.sync.m16n8k16.f16, fp32
// accumulate), ldmatrix fragment loads (single buffer — R16 showed a double
// buffer busts the 128-reg budget), cp.async pipeline with BK=64 k-tiles to
// halve barrier frequency. Weights pre-transposed to half [N,K]; activations
// flow as half. B=16384, X=64, U=16, Z=32, H=1024, A=256.
// ---------------------------------------------------------------------------

#define KDT 0.02f
#define BATCH 16384

// Scratch (allocation-free rule: __device__ globals).
__device__ __half g_bufA[BATCH * 1024];
__device__ __half g_bufB[BATCH * 1024];
__device__ __half g_s1[BATCH * 256];
__device__ __half g_s2[BATCH * 256];
__device__ float  g_z[BATCH * 32];
__device__ float  g_aux[BATCH * 32];
__device__ __half g_Bmat[BATCH * 512];
__device__ __half g_znext[BATCH * 32];
__device__ __half g_xh[BATCH * 64];         // half-converted x
__device__ __half g_wh[3645440];            // half, transposed [N,K] weights

__device__ __forceinline__ void mma16(float* d, const uint32_t* a, const uint32_t* b) {
    asm volatile(
        "mma.sync.aligned.m16n8k16.row.col.f32.f16.f16.f32 "
        "{%0,%1,%2,%3}, {%4,%5,%6,%7}, {%8,%9}, {%0,%1,%2,%3};"
        : "+f"(d[0]), "+f"(d[1]), "+f"(d[2]), "+f"(d[3])
        : "r"(a[0]), "r"(a[1]), "r"(a[2]), "r"(a[3]), "r"(b[0]), "r"(b[1]));
}

__device__ __forceinline__ void ldsm4(uint32_t& r0, uint32_t& r1,
                                      uint32_t& r2, uint32_t& r3, uint32_t addr) {
    asm volatile("ldmatrix.sync.aligned.m8n8.x4.shared.b16 {%0,%1,%2,%3}, [%4];"
                 : "=r"(r0), "=r"(r1), "=r"(r2), "=r"(r3) : "r"(addr));
}

__device__ __forceinline__ void cpa16(uint32_t dst, const void* src) {
    asm volatile("cp.async.cg.shared.global [%0], [%1], 16;" :: "r"(dst), "l"(src));
}
__device__ __forceinline__ void cpa_commit() {
    asm volatile("cp.async.commit_group;" ::: "memory");
}
template <int N>
__device__ __forceinline__ void cpa_wait() {
    asm volatile("cp.async.wait_group %0;" :: "n"(N) : "memory");
}

// ---------------------------------------------------------------------------
// Prep 1: convert x to half.
// ---------------------------------------------------------------------------
__global__ void convert_x(const float4* __restrict__ src,
                          __half2* __restrict__ dst, int n4)
{
    int i = blockIdx.x * blockDim.x + threadIdx.x;
    const int stride = gridDim.x * blockDim.x;
    for (; i < n4; i += stride) {
        float4 v = src[i];
        dst[i * 2 + 0] = __floats2half2_rn(v.x, v.y);
        dst[i * 2 + 1] = __floats2half2_rn(v.z, v.w);
    }
}

// ---------------------------------------------------------------------------
// Prep 2: transpose + convert — WT[n][k] = half(W[k][n]) for ALL 13 weights.
// ---------------------------------------------------------------------------
#define NTSEG 13
struct TSeg { const float* src; __half* dst; int K; int N; };
struct TSegPack { TSeg s[NTSEG]; };

__global__ void transpose_half(TSegPack p)
{
    const TSeg sg = p.s[blockIdx.z];
    const int n0 = blockIdx.x * 32, k0 = blockIdx.y * 32;
    if (n0 >= sg.N || k0 >= sg.K) return;
    __shared__ float tile[32][33];
    const int x = threadIdx.x, y = threadIdx.y;
#pragma unroll
    for (int i = 0; i < 4; i++)
        tile[y + i * 8][x] = sg.src[(size_t)(k0 + y + i * 8) * sg.N + n0 + x];
    __syncthreads();
#pragma unroll
    for (int i = 0; i < 4; i++)
        sg.dst[(size_t)(n0 + y + i * 8) * sg.K + k0 + x] =
            __float2half_rn(tile[x][y + i * 8]);
}

// ---------------------------------------------------------------------------
// C = act(A[M,K] @ WT[N,K]^T + bias). A half row-major, WT half [N,K].
// BM=128, 8 warps, template BK (32 or 64) and S stages. One __syncthreads
// per k-tile: wait_group(S-2); sync; issue(t+S-1); compute BK/16 k-steps.
// issue(t+S-1) overwrites stage (t-1)%S whose last reads preceded sync(t).
// Row stride = BK/2+4 words: ldmatrix phases and frag gathers conflict-free.
// OUTH: store half (feeds next GEMM); else float.
// ---------------------------------------------------------------------------
template <int BN, int BK, int S, int WM, int WN, bool ACT, bool OUTH>
__global__ void __launch_bounds__(256, 2)
gemm_fp16(const __half* __restrict__ A, const __half* __restrict__ WT,
          const float* __restrict__ bias, void* __restrict__ Cv,
          int M, int N, int K)
{
    constexpr int BM = 128;
    constexpr int MT = WM / 16;
    constexpr int NT = WN / 8;
    static_assert(NT % 2 == 0, "B ldmatrix.x4 covers n-tile pairs");
    constexpr int WARPS_N = BN / WN;
    constexpr int WARPS_M = 8 / WARPS_N;
    static_assert(WARPS_M * WM == BM, "warp grid must tile BM exactly");
    static_assert(WARPS_N * WN == BN, "warp grid must tile BN exactly");
    constexpr int STR = BK / 2 + 4;               // words per row (A and WT)
    constexpr int CPR = BK / 8;                   // 16B chunks per row
    constexpr int KS  = BK / 16;                  // k16 steps per tile
    constexpr int AWORDS = BM * STR;
    constexpr int WWORDS = BN * STR;
    constexpr int AV = (BM * CPR) / 256;
    constexpr int WTOT = BN * CPR;
    constexpr int WV = (WTOT + 255) / 256;
    constexpr bool WGUARD = (WTOT % 256) != 0;

    extern __shared__ uint32_t smem_dyn[];
    uint32_t* Asm = smem_dyn;
    uint32_t* Wsm = smem_dyn + S * AWORDS;

    const int tid  = threadIdx.x;
    const int lane = tid & 31;
    const int wid  = tid >> 5;
    const int wm   = wid / WARPS_N;
    const int wn   = wid % WARPS_N;
    const int brow = blockIdx.y * BM;
    const int bcol = blockIdx.x * BN;
    const int g    = lane >> 2;
    const int tg   = lane & 3;

    // ldmatrix lane roles (quadrant q = lane/8, r = lane%8).
    const int q  = lane >> 3;
    const int rr = lane & 7;
    const int a_row = ((q & 1) << 3) + rr;
    const int a_col = (q >> 1) << 2;
    const int b_row = ((q >> 1) << 3) + rr;
    const int b_col = (q & 1) << 2;

    const uint32_t a_sm = (uint32_t)__cvta_generic_to_shared(Asm);
    const uint32_t w_sm = (uint32_t)__cvta_generic_to_shared(Wsm);
    const int nk = K / BK;

    float acc[MT][NT][4];
#pragma unroll
    for (int m = 0; m < MT; m++)
#pragma unroll
        for (int n = 0; n < NT; n++)
#pragma unroll
            for (int qq = 0; qq < 4; qq++) acc[m][n][qq] = 0.0f;

    auto issue_tile = [&](int t) {
        if (t < nk) {
            const int s  = t % S;
            const int k0 = t * BK;
            const uint32_t ab = a_sm + (uint32_t)s * AWORDS * 4;
            const uint32_t wb = w_sm + (uint32_t)s * WWORDS * 4;
#pragma unroll
            for (int v = 0; v < AV; v++) {
                int idx = tid + v * 256;
                int row = idx / CPR, ch = idx % CPR;
                cpa16(ab + (uint32_t)(row * STR + ch * 4) * 4,
                      A + (size_t)(brow + row) * K + k0 + ch * 8);
            }
#pragma unroll
            for (int v = 0; v < WV; v++) {
                int idx = tid + v * 256;
                if (!WGUARD || idx < WTOT) {
                    int row = idx / CPR, ch = idx % CPR;
                    cpa16(wb + (uint32_t)(row * STR + ch * 4) * 4,
                          WT + (size_t)(bcol + row) * K + k0 + ch * 8);
                }
            }
        }
        cpa_commit();
    };

#pragma unroll
    for (int i = 0; i < S - 1; i++) issue_tile(i);

    for (int t = 0; t < nk; t++) {
        const int s = t % S;
        cpa_wait<S - 2>();               // tile t resident
        __syncthreads();
        issue_tile(t + S - 1);           // stage (t-1)%S: last reads preceded sync

        const uint32_t a_st = a_sm + (uint32_t)s * AWORDS * 4;
        const uint32_t w_st = w_sm + (uint32_t)s * WWORDS * 4;

#pragma unroll
        for (int ks = 0; ks < KS; ks++) {
            uint32_t af[MT][4];
#pragma unroll
            for (int m = 0; m < MT; m++) {
                const int r0 = wm * WM + m * 16;
                ldsm4(af[m][0], af[m][1], af[m][2], af[m][3],
                      a_st + (uint32_t)((r0 + a_row) * STR + ks * 8 + a_col) * 4);
            }
            uint32_t bf[NT][2];
#pragma unroll
            for (int p = 0; p < NT / 2; p++) {
                const int cb0 = wn * WN + p * 16;
                ldsm4(bf[2 * p][0], bf[2 * p][1], bf[2 * p + 1][0], bf[2 * p + 1][1],
                      w_st + (uint32_t)((cb0 + b_row) * STR + ks * 8 + b_col) * 4);
            }
#pragma unroll
            for (int m = 0; m < MT; m++)
#pragma unroll
                for (int n = 0; n < NT; n++)
                    mma16(acc[m][n], af[m], bf[n]);
        }
    }

    // ---- epilogue: bias (+ SiLU); store half or float ----
#pragma unroll
    for (int m = 0; m < MT; m++) {
#pragma unroll
        for (int n = 0; n < NT; n++) {
            const int r0 = brow + wm * WM + m * 16 + g;
            const int cc = bcol + wn * WN + n * 8 + tg * 2;
            const float b0 = bias[cc], b1 = bias[cc + 1];
            float v0 = acc[m][n][0] + b0;
            float v1 = acc[m][n][1] + b1;
            float v2 = acc[m][n][2] + b0;
            float v3 = acc[m][n][3] + b1;
            if (ACT) {
                v0 = v0 / (1.0f + __expf(-v0));
                v1 = v1 / (1.0f + __expf(-v1));
                v2 = v2 / (1.0f + __expf(-v2));
                v3 = v3 / (1.0f + __expf(-v3));
            }
            if (OUTH) {
                __half* C = (__half*)Cv;
                *reinterpret_cast<__half2*>(C + (size_t)r0 * N + cc) =
                    __floats2half2_rn(v0, v1);
                *reinterpret_cast<__half2*>(C + (size_t)(r0 + 8) * N + cc) =
                    __floats2half2_rn(v2, v3);
            } else {
                float* C = (float*)Cv;
                float2 lo = {v0, v1}, hi = {v2, v3};
                *reinterpret_cast<float2*>(C + (size_t)r0 * N + cc) = lo;
                *reinterpret_cast<float2*>(C + (size_t)(r0 + 8) * N + cc) = hi;
            }
        }
    }
}

// ---------------------------------------------------------------------------
// Combine: z_next = half(z + DT*(Az + Bu)); Bmat is half.
// ---------------------------------------------------------------------------
__global__ void combine_kernel(const float* __restrict__ z,
                               const float* __restrict__ aux,
                               const __half* __restrict__ Bmat,
                               const float* __restrict__ u,
                               __half* __restrict__ z_next)
{
    const int row  = blockIdx.x * (blockDim.x >> 5) + (threadIdx.x >> 5);
    const int lane = threadIdx.x & 31;
    if (row >= BATCH) return;

    const int j = lane;
    const int i = j >> 1;

    const float a  = aux[row * 32 + 2 * i];
    const float bb = aux[row * 32 + 2 * i + 1];
    const float z0 = z[row * 32 + 2 * i];
    const float z1 = z[row * 32 + 2 * i + 1];

    const float f = expf(a * KDT);
    const float c = cosf(bb * KDT);
    const float s = sinf(bb * KDT);

    const float az = (j & 1) ? f * (s * z0 + c * z1)
                             : f * (c * z0 - s * z1);
    const float zj = (j & 1) ? z1 : z0;

    const __half2* bm = reinterpret_cast<const __half2*>(
        Bmat + (size_t)row * 512 + j * 16);
    const float* ur = u + (size_t)row * 16;
    float bu = 0.0f;
#pragma unroll
    for (int k = 0; k < 8; k++) {
        float2 w = __half22float2(bm[k]);
        bu = fmaf(w.x, ur[2 * k],     bu);
        bu = fmaf(w.y, ur[2 * k + 1], bu);
    }

    z_next[row * 32 + j] = __float2half_rn(zj + KDT * (az + bu));
}

// ---------------------------------------------------------------------------
static constexpr int smem_fp16(int BN, int BK, int S) {
    return S * (128 + BN) * (BK / 2 + 4) * 4;
}

extern "C" void kernel_launch(void* const* d_in, const int* in_sizes, int n_in,
                              void* d_out, int out_size)
{
    const float* x    = (const float*)d_in[0];
    const float* u    = (const float*)d_in[1];
    const float* e_w1 = (const float*)d_in[2];
    const float* e_b1 = (const float*)d_in[3];
    const float* e_w2 = (const float*)d_in[4];
    const float* e_b2 = (const float*)d_in[5];
    const float* e_w3 = (const float*)d_in[6];
    const float* e_b3 = (const float*)d_in[7];
    const float* d_w1 = (const float*)d_in[8];
    const float* d_b1 = (const float*)d_in[9];
    const float* d_w2 = (const float*)d_in[10];
    const float* d_b2 = (const float*)d_in[11];
    const float* d_w3 = (const float*)d_in[12];
    const float* d_b3 = (const float*)d_in[13];
    const float* d_w4 = (const float*)d_in[14];
    const float* d_b4 = (const float*)d_in[15];
    const float* a_w1 = (const float*)d_in[16];
    const float* a_b1 = (const float*)d_in[17];
    const float* a_w2 = (const float*)d_in[18];
    const float* a_b2 = (const float*)d_in[19];
    const float* a_w3 = (const float*)d_in[20];
    const float* a_b3 = (const float*)d_in[21];
    const float* b_w1 = (const float*)d_in[22];
    const float* b_b1 = (const float*)d_in[23];
    const float* b_w2 = (const float*)d_in[24];
    const float* b_b2 = (const float*)d_in[25];
    const float* b_w3 = (const float*)d_in[26];
    const float* b_b3 = (const float*)d_in[27];
    float* out = (float*)d_out;

    __half *bufA, *bufB, *s1, *s2, *zn, *xh, *wh, *Bm;
    float  *zb, *auxb;
    cudaGetSymbolAddress((void**)&bufA, g_bufA);
    cudaGetSymbolAddress((void**)&bufB, g_bufB);
    cudaGetSymbolAddress((void**)&s1,   g_s1);
    cudaGetSymbolAddress((void**)&s2,   g_s2);
    cudaGetSymbolAddress((void**)&zb,   g_z);
    cudaGetSymbolAddress((void**)&auxb, g_aux);
    cudaGetSymbolAddress((void**)&Bm,   g_Bmat);
    cudaGetSymbolAddress((void**)&zn,   g_znext);
    cudaGetSymbolAddress((void**)&xh,   g_xh);
    cudaGetSymbolAddress((void**)&wh,   g_wh);

    // Transposed half weights in g_wh (offsets in halves).
    __half* e_w1t = wh + 0;          // [1024][64]
    __half* e_w2t = wh + 65536;      // [1024][1024]
    __half* e_w3t = wh + 1114112;    // [32][1024]
    __half* d_w1t = wh + 1146880;    // [1024][32]
    __half* d_w2t = wh + 1179648;    // [1024][1024]
    __half* d_w3t = wh + 2228224;    // [1024][1024]
    __half* d_w4t = wh + 3276800;    // [64][1024]
    __half* a_w1t = wh + 3342336;    // [256][64]
    __half* a_w2t = wh + 3358720;    // [256][256]
    __half* a_w3t = wh + 3424256;    // [32][256]
    __half* b_w1t = wh + 3432448;    // [256][64]
    __half* b_w2t = wh + 3448832;    // [256][256]
    __half* b_w3t = wh + 3514368;    // [512][256]

    // ---- prep: convert x + transpose/convert all weights (2 launches) ----
    convert_x<<<256, 256>>>((const float4*)x, (__half2*)xh, BATCH * 64 / 4);
    {
        TSegPack p;
        auto set = [&](int i, const float* s, __half* d, int K, int N) {
            p.s[i].src = s; p.s[i].dst = d; p.s[i].K = K; p.s[i].N = N;
        };
        set(0,  e_w1, e_w1t,   64, 1024);
        set(1,  e_w2, e_w2t, 1024, 1024);
        set(2,  e_w3, e_w3t, 1024,   32);
        set(3,  d_w1, d_w1t,   32, 1024);
        set(4,  d_w2, d_w2t, 1024, 1024);
        set(5,  d_w3, d_w3t, 1024, 1024);
        set(6,  d_w4, d_w4t, 1024,   64);
        set(7,  a_w1, a_w1t,   64,  256);
        set(8,  a_w2, a_w2t,  256,  256);
        set(9,  a_w3, a_w3t,  256,   32);
        set(10, b_w1, b_w1t,   64,  256);
        set(11, b_w2, b_w2t,  256,  256);
        set(12, b_w3, b_w3t,  256,  512);
        transpose_half<<<dim3(32, 32, NTSEG), dim3(32, 8)>>>(p);
    }

    const int B  = BATCH;
    const int GY = B / 128;
    const dim3 blk(256);

    // BK=64/S=3 everywhere K allows; d_w1 (K=32) uses the BK=32/S=4 config.
    constexpr int SM_BIG64 = smem_fp16(128, 64, 3);   // 110,592 B
    constexpr int SM_BIG32 = smem_fp16(128, 32, 4);   //  81,920 B
    constexpr int SM_MID   = smem_fp16( 64, 64, 3);   //  82,944 B
    constexpr int SM_SMALL = smem_fp16( 32, 64, 3);   //  69,120 B

    auto big_t   = gemm_fp16<128, 64, 3, 64, 32, true,  true >;
    auto big_h   = gemm_fp16<128, 64, 3, 64, 32, false, true >;   // b_w3
    auto big32_t = gemm_fp16<128, 32, 4, 64, 32, true,  true >;   // d_w1 (K=32)
    auto mid_f   = gemm_fp16< 64, 64, 3, 32, 32, false, false>;   // d_w4
    auto small_f = gemm_fp16< 32, 64, 3, 16, 32, false, false>;   // e_w3/a_w3

    cudaFuncSetAttribute(big_t,   cudaFuncAttributeMaxDynamicSharedMemorySize, SM_BIG64);
    cudaFuncSetAttribute(big_h,   cudaFuncAttributeMaxDynamicSharedMemorySize, SM_BIG64);
    cudaFuncSetAttribute(big32_t, cudaFuncAttributeMaxDynamicSharedMemorySize, SM_BIG32);
    cudaFuncSetAttribute(mid_f,   cudaFuncAttributeMaxDynamicSharedMemorySize, SM_MID);
    cudaFuncSetAttribute(small_f, cudaFuncAttributeMaxDynamicSharedMemorySize, SM_SMALL);

    // ---- encoder: x -> h1 -> h2 -> z ----
    big_t  <<<dim3(8, GY), blk, SM_BIG64>>>(xh,   e_w1t, e_b1, bufA, B, 1024,   64);
    big_t  <<<dim3(8, GY), blk, SM_BIG64>>>(bufA, e_w2t, e_b2, bufB, B, 1024, 1024);
    small_f<<<dim3(1, GY), blk, SM_SMALL>>>(bufB, e_w3t, e_b3, zb,   B,   32, 1024);

    // ---- aux net ----
    big_t  <<<dim3(2, GY), blk, SM_BIG64>>>(xh, a_w1t, a_b1, s1,   B, 256,  64);
    big_t  <<<dim3(2, GY), blk, SM_BIG64>>>(s1, a_w2t, a_b2, s2,   B, 256, 256);
    small_f<<<dim3(1, GY), blk, SM_SMALL>>>(s2, a_w3t, a_b3, auxb, B,  32, 256);

    // ---- B net ----
    big_t  <<<dim3(2, GY), blk, SM_BIG64>>>(xh, b_w1t, b_b1, s1, B, 256,  64);
    big_t  <<<dim3(2, GY), blk, SM_BIG64>>>(s1, b_w2t, b_b2, s2, B, 256, 256);
    big_h  <<<dim3(4, GY), blk, SM_BIG64>>>(s2, b_w3t, b_b3, Bm, B, 512, 256);

    // ---- dynamics combine (half z_next for decoder) ----
    combine_kernel<<<B / 8, 256>>>(zb, auxb, Bm, u, zn);

    // ---- decoder ----
    big32_t<<<dim3(8, GY), blk, SM_BIG32>>>(zn,   d_w1t, d_b1, bufA, B, 1024,   32);
    big_t  <<<dim3(8, GY), blk, SM_BIG64>>>(bufA, d_w2t, d_b2, bufB, B, 1024, 1024);
    big_t  <<<dim3(8, GY), blk, SM_BIG64>>>(bufB, d_w3t, d_b3, bufA, B, 1024, 1024);
    mid_f  <<<dim3(1, GY), blk, SM_MID  >>>(bufA, d_w4t, d_b4, out,  B,   64, 1024);
}